// round 4
// baseline (speedup 1.0000x reference)
#include <cuda_runtime.h>
#include <cuda_bf16.h>

// Causal BoW = running mean along T. Shapes: B=32, T=2048, C=512, fp32.
//
// Single-pass decoupled-lookback scan, windowed (CUB-style):
//  tile = (chain, tk): chain = (b, c-half) -> 64 chains; tk = chunk of
//  R=16 rows -> 128 chunks/chain; 8192 tiles.
//  256-thread CTA = one thread per column, 16 rows in registers.
//  Lookback: warp 0 polls up to 32 predecessor flags per batch
//  (ld.acquire.gpu); all threads then load the whole valid window of
//  per-column values as independent L2 reads. Atomic ticket gives tiles
//  scheduling order -> deadlock-free (aggregates publish before lookback).

#define B_DIM 32
#define T_DIM 2048
#define C_DIM 512
#define R_ROWS 16
#define CGROUP 256
#define NCHAINS (B_DIM * (C_DIM / CGROUP))   // 64
#define NTK (T_DIM / R_ROWS)                 // 128
#define NTILES (NCHAINS * NTK)               // 8192
#define WND 32

__device__ float g_aggr[(size_t)NTILES * CGROUP];   // 8 MB
__device__ float g_incl[(size_t)NTILES * CGROUP];   // 8 MB
__device__ int   g_flag[NTILES];                     // 0=none 1=aggr 2=incl
__device__ unsigned int g_ticket;

__device__ __forceinline__ int ld_acquire(const int* p) {
    int v;
    asm volatile("ld.global.acquire.gpu.b32 %0, [%1];" : "=r"(v) : "l"(p) : "memory");
    return v;
}

__global__ void clear_kernel() {
    int i = blockIdx.x * blockDim.x + threadIdx.x;   // 8192 threads
    g_flag[i] = 0;
    if (i == 0) g_ticket = 0u;
}

__global__ __launch_bounds__(CGROUP, 6)
void causal_bow_scan(const float* __restrict__ x, float* __restrict__ out) {
    __shared__ unsigned s_tile;
    __shared__ int s_flags[WND];
    __shared__ float s_inv[R_ROWS];

    const int tid = threadIdx.x;
    if (tid == 0) s_tile = atomicAdd(&g_ticket, 1u);
    __syncthreads();

    const unsigned vt = s_tile;
    const unsigned chain = vt % NCHAINS;
    const unsigned tk = vt / NCHAINS;
    const unsigned b  = chain >> 1;
    const unsigned ch = chain & 1;
    const unsigned c  = ch * CGROUP + tid;
    const int t0 = tk * R_ROWS;

    if (tid < R_ROWS)
        s_inv[tid] = 1.0f / (float)(t0 + tid + 1);

    const size_t base = (size_t)b * T_DIM * C_DIM + (size_t)t0 * C_DIM + c;
    const float* __restrict__ xp = x + base;
    float* __restrict__ op = out + base;

    // Batched independent loads: 16 coalesced 128B lines in flight per warp.
    float v[R_ROWS];
    #pragma unroll
    for (int u = 0; u < R_ROWS; ++u)
        v[u] = __ldg(xp + (size_t)u * C_DIM);

    // Local inclusive scan in registers.
    #pragma unroll
    for (int u = 1; u < R_ROWS; ++u)
        v[u] += v[u - 1];
    const float total = v[R_ROWS - 1];

    const size_t slot = (size_t)vt * CGROUP + tid;
    float prefix = 0.0f;

    if (tk == 0) {
        __stcg(&g_incl[slot], total);
        __threadfence();
        __syncthreads();
        if (tid == 0) __stcg(&g_flag[vt], 2);
    } else {
        // Publish aggregate first (unconditional progress -> deadlock-free).
        __stcg(&g_aggr[slot], total);
        __threadfence();
        __syncthreads();
        if (tid == 0) __stcg(&g_flag[vt], 1);

        // Windowed lookback: poll up to WND predecessor flags per batch.
        int pbase = (int)vt - NCHAINS;       // nearest unconsumed predecessor
        while (true) {
            if (tid < WND) {
                int j = pbase - tid * NCHAINS;
                s_flags[tid] = (j >= 0) ? ld_acquire(&g_flag[j]) : 0;
            }
            __syncthreads();

            // Leading-valid window (identical computation in every thread).
            int ncons = 0, widx = -1;
            #pragma unroll
            for (int i = 0; i < WND; ++i) {
                int f = s_flags[i];
                if (widx < 0 && ncons == i) {
                    if (f == 2) { widx = i; ncons = i + 1; }
                    else if (f == 1) { ncons = i + 1; }
                }
            }
            // ncons counts leading entries with f>=1 up to & incl. first f==2.

            // Consume window values: independent L2 loads, pipelined.
            #pragma unroll
            for (int i = 0; i < WND; ++i) {
                if (i < ncons) {
                    int j = pbase - i * NCHAINS;
                    const float* src = (i == widx) ? g_incl : g_aggr;
                    prefix += __ldcg(src + (size_t)j * CGROUP + tid);
                }
            }

            if (widx >= 0) break;
            pbase -= ncons * NCHAINS;
            __syncthreads();   // protect s_flags before re-poll
        }

        __stcg(&g_incl[slot], prefix + total);
        __threadfence();
        __syncthreads();
        if (tid == 0) __stcg(&g_flag[vt], 2);
    }

    // Scaled output, streaming stores (don't pollute L2).
    #pragma unroll
    for (int u = 0; u < R_ROWS; ++u)
        __stcs(op + (size_t)u * C_DIM, (prefix + v[u]) * s_inv[u]);
}

extern "C" void kernel_launch(void* const* d_in, const int* in_sizes, int n_in,
                              void* d_out, int out_size) {
    const float* x = (const float*)d_in[0];
    float* out = (float*)d_out;
    (void)in_sizes; (void)n_in; (void)out_size;

    clear_kernel<<<NTILES / 256, 256>>>();
    causal_bow_scan<<<NTILES, CGROUP>>>(x, out);
}

// round 5
// speedup vs baseline: 2.4746x; 2.4746x over previous
#include <cuda_runtime.h>
#include <cuda_bf16.h>

// Causal BoW = running mean along T. Shapes: B=32, T=2048, C=512, fp32.
//
// Single-pass CHAINED scan (decoupled-lookback degenerated to depth-1,
// which R3 profiling showed is the common case anyway):
//  tile = (chain, tk): chain = (b, c-half) -> 64 chains; tk = chunk of
//  R=32 rows -> 64 chunks/chain; 4096 tiles.
//  256-thread CTA = one thread per column, 32 rows in registers.
//  Per-column inclusive prefixes are published as ONE packed 64-bit word
//  (status<<32 | float bits) via atomicExch -> single-word atomicity, no
//  fences, no flag/value split. Successor threads spin independently with
//  volatile 64-bit loads: chain step ~= one L2 round-trip.
//  Atomic ticket = scheduling order -> predecessor always resident/done.

#define B_DIM 32
#define T_DIM 2048
#define C_DIM 512
#define R_ROWS 32
#define CGROUP 256
#define NCHAINS (B_DIM * (C_DIM / CGROUP))   // 64
#define NTK (T_DIM / R_ROWS)                 // 64
#define NTILES (NCHAINS * NTK)               // 4096

__device__ unsigned long long g_incl[(size_t)NTILES * CGROUP];  // 8 MB packed
__device__ unsigned int g_ticket;

__global__ void clear_kernel() {
    size_t i = (size_t)blockIdx.x * blockDim.x + threadIdx.x;
    size_t stride = (size_t)gridDim.x * blockDim.x;
    size_t total = (size_t)NTILES * CGROUP;
    for (size_t k = i; k < total; k += stride)
        g_incl[k] = 0ull;
    if (i == 0) g_ticket = 0u;
}

__global__ __launch_bounds__(CGROUP)
void causal_bow_scan(const float* __restrict__ x, float* __restrict__ out) {
    __shared__ unsigned s_tile;
    __shared__ float s_inv[R_ROWS];

    const int tid = threadIdx.x;
    if (tid == 0) s_tile = atomicAdd(&g_ticket, 1u);
    __syncthreads();

    const unsigned vt = s_tile;
    const unsigned chain = vt % NCHAINS;
    const unsigned tk = vt / NCHAINS;
    const unsigned b  = chain >> 1;
    const unsigned ch = chain & 1;
    const unsigned c  = ch * CGROUP + tid;
    const int t0 = tk * R_ROWS;

    if (tid < R_ROWS)
        s_inv[tid] = 1.0f / (float)(t0 + tid + 1);

    const size_t base = (size_t)b * T_DIM * C_DIM + (size_t)t0 * C_DIM + c;
    const float* __restrict__ xp = x + base;
    float* __restrict__ op = out + base;

    // Batched independent loads: 32 coalesced 128B lines in flight per warp.
    float v[R_ROWS];
    #pragma unroll
    for (int u = 0; u < R_ROWS; ++u)
        v[u] = __ldg(xp + (size_t)u * C_DIM);

    // Local inclusive scan in registers.
    #pragma unroll
    for (int u = 1; u < R_ROWS; ++u)
        v[u] += v[u - 1];

    // Resolve prefix: per-thread spin on predecessor's packed word.
    float prefix = 0.0f;
    if (tk != 0) {
        const volatile unsigned long long* pred =
            &g_incl[(size_t)(vt - NCHAINS) * CGROUP + tid];
        unsigned long long pk;
        do { pk = *pred; } while ((pk >> 32) == 0ull);
        prefix = __uint_as_float((unsigned)(pk & 0xFFFFFFFFu));
    }

    // Publish own inclusive prefix (single 8B atomic word: flag+value).
    {
        const float incl = prefix + v[R_ROWS - 1];
        unsigned long long pk = (1ull << 32)
                              | (unsigned long long)__float_as_uint(incl);
        atomicExch(&g_incl[(size_t)vt * CGROUP + tid], pk);
    }

    __syncthreads();   // s_inv ready

    // Scaled output: (prefix + local inclusive) / (t+1).
    #pragma unroll
    for (int u = 0; u < R_ROWS; ++u)
        op[(size_t)u * C_DIM] = (prefix + v[u]) * s_inv[u];
}

extern "C" void kernel_launch(void* const* d_in, const int* in_sizes, int n_in,
                              void* d_out, int out_size) {
    const float* x = (const float*)d_in[0];
    float* out = (float*)d_out;
    (void)in_sizes; (void)n_in; (void)out_size;

    clear_kernel<<<1024, 256>>>();
    causal_bow_scan<<<NTILES, CGROUP>>>(x, out);
}

// round 6
// speedup vs baseline: 2.4846x; 1.0040x over previous
#include <cuda_runtime.h>
#include <cuda_bf16.h>

// Causal BoW = running mean along T. Shapes: B=32, T=2048, C=512, fp32.
//
// Single-pass CHAINED scan, SELF-CLEANING (no clear kernel):
//  tile = (chain, tk): chain = (b, c-half) -> 64 chains; tk = chunk of
//  R=32 rows -> 64 chunks/chain; 4096 tiles.
//  256-thread CTA = one thread per column, 32 rows in registers.
//  Per-column inclusive prefixes published as ONE packed 64-bit word
//  (status<<32 | float bits) via atomicExch. Successor threads spin with
//  volatile 64-bit loads, then RESET the slot to 0 (consume-and-reset).
//  Last chunk (tk=NTK-1) never publishes (no successor). The CTA that
//  draws the final ticket resets g_ticket (all atomicAdds on that address
//  have serialized before it). => all device state returns to zero after
//  every launch: deterministic, graph-safe, zero auxiliary kernels.

#define B_DIM 32
#define T_DIM 2048
#define C_DIM 512
#define R_ROWS 32
#define CGROUP 256
#define NCHAINS (B_DIM * (C_DIM / CGROUP))   // 64
#define NTK (T_DIM / R_ROWS)                 // 64
#define NTILES (NCHAINS * NTK)               // 4096

__device__ unsigned long long g_incl[(size_t)NTILES * CGROUP];  // 8 MB packed
__device__ unsigned int g_ticket;

__global__ __launch_bounds__(CGROUP)
void causal_bow_scan(const float* __restrict__ x, float* __restrict__ out) {
    __shared__ unsigned s_tile;
    __shared__ float s_inv[R_ROWS];

    const int tid = threadIdx.x;
    if (tid == 0) {
        unsigned t = atomicAdd(&g_ticket, 1u);
        s_tile = t;
        // Last ticket drawn -> every atomicAdd on g_ticket has completed
        // (same-address atomics serialize). Safe to reset for next launch.
        if (t == NTILES - 1) atomicExch(&g_ticket, 0u);
    }
    __syncthreads();

    const unsigned vt = s_tile;
    const unsigned chain = vt % NCHAINS;
    const unsigned tk = vt / NCHAINS;
    const unsigned b  = chain >> 1;
    const unsigned ch = chain & 1;
    const unsigned c  = ch * CGROUP + tid;
    const int t0 = tk * R_ROWS;

    if (tid < R_ROWS)
        s_inv[tid] = 1.0f / (float)(t0 + tid + 1);

    const size_t base = (size_t)b * T_DIM * C_DIM + (size_t)t0 * C_DIM + c;
    const float* __restrict__ xp = x + base;
    float* __restrict__ op = out + base;

    // Batched independent loads: 32 coalesced 128B lines in flight per warp.
    // Streaming hint: read-once data, keep L2 for the protocol scratch.
    float v[R_ROWS];
    #pragma unroll
    for (int u = 0; u < R_ROWS; ++u)
        v[u] = __ldcs(xp + (size_t)u * C_DIM);

    // Local inclusive scan in registers.
    #pragma unroll
    for (int u = 1; u < R_ROWS; ++u)
        v[u] += v[u - 1];

    __syncthreads();   // s_inv ready (off the inter-CTA critical tail)

    // Resolve prefix: per-thread spin on predecessor's packed word, then
    // consume-and-reset so the slot is zero for the next launch.
    float prefix = 0.0f;
    if (tk != 0) {
        unsigned long long* predp =
            &g_incl[(size_t)(vt - NCHAINS) * CGROUP + tid];
        unsigned long long pk;
        do { pk = *(volatile unsigned long long*)predp; }
        while ((pk >> 32) == 0ull);
        prefix = __uint_as_float((unsigned)(pk & 0xFFFFFFFFu));
        *(volatile unsigned long long*)predp = 0ull;   // consume-reset
    }

    // Publish own inclusive prefix — except the last chunk (no successor).
    if (tk != NTK - 1) {
        const float incl = prefix + v[R_ROWS - 1];
        unsigned long long pk = (1ull << 32)
                              | (unsigned long long)__float_as_uint(incl);
        atomicExch(&g_incl[(size_t)vt * CGROUP + tid], pk);
    }

    // Scaled output: (prefix + local inclusive) / (t+1). Streaming stores.
    #pragma unroll
    for (int u = 0; u < R_ROWS; ++u)
        __stcs(op + (size_t)u * C_DIM, (prefix + v[u]) * s_inv[u]);
}

extern "C" void kernel_launch(void* const* d_in, const int* in_sizes, int n_in,
                              void* d_out, int out_size) {
    const float* x = (const float*)d_in[0];
    float* out = (float*)d_out;
    (void)in_sizes; (void)n_in; (void)out_size;

    causal_bow_scan<<<NTILES, CGROUP>>>(x, out);
}